// round 14
// baseline (speedup 1.0000x reference)
#include <cuda_runtime.h>
#include <cuda_fp16.h>
#include <cstdint>
#include <math.h>

// ---------------- problem constants ----------------
#define T_TOK 8192      // B*S
#define DM    1024
#define DF    4096
#define NE    8
#define GHID  512
#define LN_EPS 1e-5f
#define KG1   (3*DM)    // split-gate1 K' = 3072
#define CAP   8192      // fixed slots per expert

// ---------------- device scratch ----------------
__device__ float  g_gh[T_TOK * GHID];                 // gating hidden (fp32)
__device__ __half g_xh[(size_t)T_TOK * DM];           // fp16 x (hi)
__device__ __half g_xlo[(size_t)T_TOK * DM];          // fp16 x residual (lo)
__device__ __half g_gw1h[(size_t)GHID * KG1];         // [n=512][k'=3072] = [whi|wlo|whi]
__device__ __half g_w1h[(size_t)NE * DF * DM];        // [E][n=F][k=D]
__device__ __half g_w2h[(size_t)NE * DM * DF];        // [E][n=D][k=F]
__device__ __half g_hbuf[(size_t)NE * CAP * DF];      // fp16 hidden (fixed-capacity groups)
__device__ __half g_eo[(size_t)NE * CAP * DM];        // per-slot expert out (fp16)
__device__ int    g_cur[NE];
__device__ int    g_rdy[NE * 64];                     // exp1 row-tile completion counters
__device__ float  g_tg[T_TOK * 2];
__device__ int    g_slot[T_TOK * 2];
__device__ int    g_tok[NE * CAP];
__device__ float  g_psum[NE];

// ---------------- side stream for overlap (host-side resources only) ----------------
static cudaStream_t g_s2;
static cudaEvent_t g_evA, g_evB;
namespace {
struct StreamInit {
    StreamInit() {
        cudaStreamCreateWithFlags(&g_s2, cudaStreamNonBlocking);
        cudaEventCreateWithFlags(&g_evA, cudaEventDisableTiming);
        cudaEventCreateWithFlags(&g_evB, cudaEventDisableTiming);
    }
};
StreamInit g_si;
}

// ---------------- PTX helpers ----------------
__device__ __forceinline__ void mma_f16(float* c, const uint32_t* a, const uint32_t* b) {
    asm volatile(
        "mma.sync.aligned.m16n8k16.row.col.f32.f16.f16.f32 "
        "{%0,%1,%2,%3},{%4,%5,%6,%7},{%8,%9},{%0,%1,%2,%3};"
        : "+f"(c[0]), "+f"(c[1]), "+f"(c[2]), "+f"(c[3])
        : "r"(a[0]), "r"(a[1]), "r"(a[2]), "r"(a[3]), "r"(b[0]), "r"(b[1]));
}
__device__ __forceinline__ void ldsm4(uint32_t& a, uint32_t& b, uint32_t& c, uint32_t& d,
                                      uint32_t addr) {
    asm volatile("ldmatrix.sync.aligned.m8n8.x4.shared.b16 {%0,%1,%2,%3}, [%4];"
                 : "=r"(a), "=r"(b), "=r"(c), "=r"(d) : "r"(addr));
}
__device__ __forceinline__ void cp16(void* smem, const void* g) {
    uint32_t s = (uint32_t)__cvta_generic_to_shared(smem);
    asm volatile("cp.async.cg.shared.global [%0],[%1],16;" :: "r"(s), "l"(g));
}
__device__ __forceinline__ void cp_commit() { asm volatile("cp.async.commit_group;"); }
__device__ __forceinline__ void cp_wait1() { asm volatile("cp.async.wait_group 1;"); }
__device__ __forceinline__ void cp_wait0() { asm volatile("cp.async.wait_group 0;"); }
__device__ __forceinline__ uint32_t smem_u32(const void* p) {
    uint32_t a;
    asm("{ .reg .u64 t; cvta.to.shared.u64 t, %1; cvt.u32.u64 %0, t; }" : "=r"(a) : "l"(p));
    return a;
}

// smem geometry: rows of 32 data halves padded to 40 (conflict-free; proven R8)
#define HPITCH 40
#define BKH    32
#define STG_H   (128 * HPITCH)
#define STAGE_H (2 * STG_H)
#define NSTAGE  3
#define EXP_SMEM (NSTAGE * STAGE_H * 2)   // 61440 B dynamic

// ---------------- prep: x hi/lo split + gw1 split-transpose + counter zero ----------------
#define PREP_CVT_BLOCKS (T_TOK * DM / 4 / 256)   // 8192
__global__ void k_prep(const float* __restrict__ x, const float* __restrict__ gw1) {
    int b = blockIdx.x, tid = threadIdx.x;
    if (b < PREP_CVT_BLOCKS) {
        if (b == 0 && tid < NE) { g_cur[tid] = 0; g_psum[tid] = 0.f; }
        if (b == 1) { g_rdy[tid] = 0; g_rdy[tid + 256] = 0; }
        int i = (b * 256 + tid) * 4;
        float4 v = *(const float4*)(x + i);
        __half h[4] = {__float2half_rn(v.x), __float2half_rn(v.y),
                       __float2half_rn(v.z), __float2half_rn(v.w)};
        __half l[4] = {__float2half_rn(v.x - __half2float(h[0])),
                       __float2half_rn(v.y - __half2float(h[1])),
                       __float2half_rn(v.z - __half2float(h[2])),
                       __float2half_rn(v.w - __half2float(h[3]))};
        *(uint2*)(g_xh + i) = *(uint2*)h;
        *(uint2*)(g_xlo + i) = *(uint2*)l;
    } else {
        __shared__ float t[32][33];
        int tb = b - PREP_CVT_BLOCKS;                 // [0, 512)
        int c0 = (tb & 15) * 32, r0 = (tb >> 4) * 32; // c = n, r = k
        int tx = tid & 31, ty = tid >> 5;
#pragma unroll
        for (int i = 0; i < 32; i += 8)
            t[ty + i][tx] = gw1[(size_t)(r0 + ty + i) * GHID + c0 + tx];
        __syncthreads();
#pragma unroll
        for (int i = 0; i < 32; i += 8) {
            int n = c0 + ty + i, k = r0 + tx;
            float v = t[tx][ty + i];
            __half hi = __float2half_rn(v);
            __half lo = __float2half_rn(v - __half2float(hi));
            g_gw1h[(size_t)n * KG1 + k] = hi;
            g_gw1h[(size_t)n * KG1 + DM + k] = lo;
            g_gw1h[(size_t)n * KG1 + 2 * DM + k] = hi;
        }
    }
}

// ---------------- weight transpose+convert: src[e][k][n] -> dst[e][n][k] fp16 ----------------
__global__ void k_trcvt(const float* __restrict__ src, __half* __restrict__ dst,
                        int R /*k*/, int C /*n*/) {
    __shared__ float t[32][33];
    size_t eb = (size_t)blockIdx.z * R * C;
    int c0 = blockIdx.x * 32, r0 = blockIdx.y * 32;
    int tx = threadIdx.x, ty = threadIdx.y;
#pragma unroll
    for (int i = 0; i < 32; i += 8)
        t[ty + i][tx] = src[eb + (size_t)(r0 + ty + i) * C + c0 + tx];
    __syncthreads();
#pragma unroll
    for (int i = 0; i < 32; i += 8)
        dst[eb + (size_t)(c0 + ty + i) * R + r0 + tx] = __float2half_rn(t[tx][ty + i]);
}

// ---------------- gating GEMM2 + top2 + softmax + fused scatter ----------------
__global__ void k_gate2(const float* __restrict__ gw2, const float* __restrict__ gb2) {
    __shared__ float s_ps[NE];
    int tid = threadIdx.x, lane = tid & 31, w = tid >> 5;
    if (tid < NE) s_ps[tid] = 0.f;
    __syncthreads();
    int t = blockIdx.x * 8 + w;
    float acc[NE] = {};
    const float* gr = g_gh + (size_t)t * GHID;
    for (int j = lane; j < GHID; j += 32) {
        float v = gr[j];
#pragma unroll
        for (int e = 0; e < NE; e++) acc[e] += v * gw2[j * NE + e];
    }
#pragma unroll
    for (int e = 0; e < NE; e++)
#pragma unroll
        for (int o = 16; o > 0; o >>= 1) acc[e] += __shfl_xor_sync(0xffffffffu, acc[e], o);
    if (lane == 0) {
        float lg[NE];
        float m = -1e30f;
#pragma unroll
        for (int e = 0; e < NE; e++) { lg[e] = acc[e] + gb2[e]; m = fmaxf(m, lg[e]); }
        int i1 = 0, i2 = -1; float v1 = -1e30f, v2 = -1e30f;
#pragma unroll
        for (int e = 0; e < NE; e++) {
            float v = lg[e];
            if (v > v1) { v2 = v1; i2 = i1; v1 = v; i1 = e; }
            else if (v > v2) { v2 = v; i2 = e; }
        }
        float ex = expf(v2 - v1);
        float inv2 = 1.f / (1.f + ex);
        g_tg[t * 2 + 0] = inv2; g_tg[t * 2 + 1] = ex * inv2;
        int p1 = atomicAdd(&g_cur[i1], 1);
        int p2 = atomicAdd(&g_cur[i2], 1);
        int s1 = i1 * CAP + p1, s2 = i2 * CAP + p2;
        g_tok[s1] = t; g_tok[s2] = t;
        g_slot[t * 2 + 0] = s1; g_slot[t * 2 + 1] = s2;
        float se = 0.f, pe[NE];
#pragma unroll
        for (int e = 0; e < NE; e++) { pe[e] = expf(lg[e] - m); se += pe[e]; }
        float inv = 1.f / se;
#pragma unroll
        for (int e = 0; e < NE; e++) atomicAdd(&s_ps[e], pe[e] * inv);
    }
    __syncthreads();
    if (tid < NE) atomicAdd(&g_psum[tid], s_ps[tid]);
}

// =======================================================================
// fp16 mma.sync GEMM body (R8-proven geometry).
// MODE 0: hbuf(fp16) = gelu(gather(xh) @ w1h^T + be1)     (K = DM)
// MODE 1: eo(fp16)  = (hbuf @ w2h^T + be2)*escale+ebias   (K = DF)
// MODE 2: gh(fp32)  = relu([xhi|xhi|xlo] @ gw1h^T + gb1)  (K = 3072)
// =======================================================================
template <int MODE>
__device__ __forceinline__ void gemm_body(__half* sm, int e, int row0, int col0, int cnt,
                                          const float* __restrict__ p1,
                                          const float* __restrict__ p2,
                                          const float* __restrict__ p3) {
    int off = (MODE == 2) ? 0 : e * CAP;
    int tid = threadIdx.x, lane = tid & 31, wid = tid >> 5;
    int m0w = (wid >> 2) * 64;
    int n0w = (wid & 3) * 32;

    const int KD = (MODE == 0) ? DM : (MODE == 1 ? DF : KG1);
    int r = tid >> 1, cp0h = (tid & 1) * 16;
    int arow = row0 + r;
    int arc = arow < cnt ? arow : cnt - 1;
    const __half* arp_hi;
    const __half* arp_lo = nullptr;
    if (MODE == 0)      arp_hi = g_xh + (size_t)g_tok[off + arc] * DM;
    else if (MODE == 1) arp_hi = g_hbuf + (size_t)(off + arc) * DF;
    else { arp_hi = g_xh + (size_t)arc * DM; arp_lo = g_xlo + (size_t)arc * DM; }
    const __half* brp = (MODE == 2)
        ? (g_gw1h + (size_t)(col0 + r) * KG1)
        : ((MODE ? g_w2h : g_w1h) + (size_t)e * DM * DF + (size_t)(col0 + r) * KD);
    int ldo = r * HPITCH + cp0h;

    int lr = lane & 7;
    int a_radd = ((lane >> 3) & 1) * 8 + lr, a_kadd = (lane >> 4) * 8;
    int b_radd = (lane >> 4) * 8 + lr, b_kadd = ((lane >> 3) & 1) * 8;
    int a_off[4], b_off[2];
#pragma unroll
    for (int mi = 0; mi < 4; mi++) a_off[mi] = (m0w + mi * 16 + a_radd) * HPITCH + a_kadd;
#pragma unroll
    for (int ni = 0; ni < 2; ni++) b_off[ni] = (n0w + ni * 16 + b_radd) * HPITCH + b_kadd;
    uint32_t smu = smem_u32(sm);

    float acc[4][4][4] = {};

    const int NIT = KD / BKH;
#pragma unroll
    for (int s = 0; s < 2; s++) {
        int k0 = s * BKH;
        const __half* as;
        if (MODE == 2) as = (k0 < 2 * DM ? arp_hi + (k0 & (DM - 1)) : arp_lo + (k0 - 2 * DM)) + cp0h;
        else           as = arp_hi + k0 + cp0h;
        __half* ad = sm + s * STAGE_H + ldo;
        __half* bd = sm + s * STAGE_H + STG_H + ldo;
        cp16(ad, as); cp16(ad + 8, as + 8);
        cp16(bd, brp + k0 + cp0h); cp16(bd + 8, brp + k0 + cp0h + 8);
        cp_commit();
    }

    int st = 0;
    for (int it = 0; it < NIT; it++) {
        if (it < NIT - 2) cp_wait1(); else cp_wait0();
        __syncthreads();
        if (it + 2 < NIT) {
            int k0 = (it + 2) * BKH;
            int ws = st + 2 >= NSTAGE ? st + 2 - NSTAGE : st + 2;
            const __half* as;
            if (MODE == 2) as = (k0 < 2 * DM ? arp_hi + (k0 & (DM - 1)) : arp_lo + (k0 - 2 * DM)) + cp0h;
            else           as = arp_hi + k0 + cp0h;
            __half* ad = sm + ws * STAGE_H + ldo;
            __half* bd = sm + ws * STAGE_H + STG_H + ldo;
            cp16(ad, as); cp16(ad + 8, as + 8);
            cp16(bd, brp + k0 + cp0h); cp16(bd + 8, brp + k0 + cp0h + 8);
            cp_commit();
        }
        uint32_t stA = smu + (uint32_t)(st * STAGE_H) * 2;
        uint32_t stB = stA + (uint32_t)STG_H * 2;
#pragma unroll
        for (int q = 0; q < BKH; q += 16) {
            uint32_t af[4][4], bf[4][2];
#pragma unroll
            for (int mi = 0; mi < 4; mi++)
                ldsm4(af[mi][0], af[mi][1], af[mi][2], af[mi][3],
                      stA + (uint32_t)(a_off[mi] + q) * 2);
#pragma unroll
            for (int np = 0; np < 2; np++)
                ldsm4(bf[2 * np][0], bf[2 * np][1], bf[2 * np + 1][0], bf[2 * np + 1][1],
                      stB + (uint32_t)(b_off[np] + q) * 2);
#pragma unroll
            for (int mi = 0; mi < 4; mi++)
#pragma unroll
                for (int ni = 0; ni < 4; ni++) mma_f16(acc[mi][ni], af[mi], bf[ni]);
        }
        st = st + 1 == NSTAGE ? 0 : st + 1;
    }

    int gr = lane >> 2, c2 = (lane & 3) * 2;
#pragma unroll
    for (int mi = 0; mi < 4; mi++) {
#pragma unroll
        for (int half = 0; half < 2; half++) {
            int rr = row0 + m0w + mi * 16 + gr + half * 8;
            if (rr < cnt) {
                if (MODE == 0) {
                    __half* orow = g_hbuf + (size_t)(off + rr) * DF;
                    const float* bb = p1 + e * DF;
#pragma unroll
                    for (int ni = 0; ni < 4; ni++) {
                        int c = col0 + n0w + ni * 8 + c2;
                        float v0 = acc[mi][ni][half * 2 + 0] + bb[c];
                        float v1 = acc[mi][ni][half * 2 + 1] + bb[c + 1];
                        v0 = 0.5f * v0 * (1.f + erff(v0 * 0.70710678118654752f));
                        v1 = 0.5f * v1 * (1.f + erff(v1 * 0.70710678118654752f));
                        *(__half2*)(orow + c) = __floats2half2_rn(v0, v1);
                    }
                } else if (MODE == 1) {
                    __half* orow = g_eo + (size_t)(off + rr) * DM;
                    const float* bb = p1 + e * DM;
                    const float* ss = p2 + e * DM;
                    const float* eb = p3 + e * DM;
#pragma unroll
                    for (int ni = 0; ni < 4; ni++) {
                        int c = col0 + n0w + ni * 8 + c2;
                        float v0 = (acc[mi][ni][half * 2 + 0] + bb[c]) * ss[c] + eb[c];
                        float v1 = (acc[mi][ni][half * 2 + 1] + bb[c + 1]) * ss[c + 1] + eb[c + 1];
                        *(__half2*)(orow + c) = __floats2half2_rn(v0, v1);
                    }
                } else {
                    float* orow = g_gh + (size_t)rr * GHID;
                    const float* bb = p1;   // gb1
#pragma unroll
                    for (int ni = 0; ni < 4; ni++) {
                        int c = col0 + n0w + ni * 8 + c2;
                        float v0 = fmaxf(acc[mi][ni][half * 2 + 0] + bb[c], 0.f);
                        float v1 = fmaxf(acc[mi][ni][half * 2 + 1] + bb[c + 1], 0.f);
                        *(float2*)(orow + c) = make_float2(v0, v1);
                    }
                }
            }
        }
    }
}

// ---------------- gating GEMM1 wrapper (MODE 2, dense) ----------------
__global__ __launch_bounds__(256, 2) void k_gate1tc(const float* __restrict__ gb1) {
    extern __shared__ __half sm[];
    gemm_body<2>(sm, 0, blockIdx.y * 128, blockIdx.x * 128, T_TOK, gb1, nullptr, nullptr);
}

// ---------------- fused expert FFN: exp1 blocks + exp2 blocks, spin-wait dependency ----------------
#define EXP1_BLOCKS (32 * 64 * NE)    // 16384
#define EXP2_BLOCKS (8 * 64 * NE)     // 4096
__global__ __launch_bounds__(256, 2) void k_exp_fused(const float* __restrict__ be1,
                                                      const float* __restrict__ be2,
                                                      const float* __restrict__ escale,
                                                      const float* __restrict__ ebias) {
    extern __shared__ __half sm[];
    int bid = blockIdx.x;
    if (bid < EXP1_BLOCKS) {
        int col = (bid & 31) * 128, row = (bid >> 5) & 63, e = bid >> 11;
        int cnt = g_cur[e];
        if (row * 128 >= cnt) return;
        gemm_body<0>(sm, e, row * 128, col, cnt, be1, nullptr, nullptr);
        __syncthreads();
        if (threadIdx.x == 0) {
            __threadfence();
            atomicAdd(&g_rdy[e * 64 + row], 1);
        }
    } else {
        int b2 = bid - EXP1_BLOCKS;
        int col = (b2 & 7) * 128, row = (b2 >> 3) & 63, e = b2 >> 9;
        int cnt = g_cur[e];
        if (row * 128 >= cnt) return;
        if (threadIdx.x == 0) {
            while (*(volatile int*)&g_rdy[e * 64 + row] < 32) __nanosleep(64);
            __threadfence();
        }
        __syncthreads();
        gemm_body<1>(sm, e, row * 128, col, cnt, be2, escale, ebias);
    }
}

// ---------------- final: combine top-2 + residual + LayerNorm + loss (float4/half2) ----------------
__global__ void k_ln(const float* __restrict__ x, const float* __restrict__ gamma,
                     const float* __restrict__ beta, float* __restrict__ out, int out_size) {
    int t = blockIdx.x;
    int tid = threadIdx.x;
    __shared__ float red[8];
    int c = tid * 4;
    const float4 x4 = *(const float4*)(x + (size_t)t * DM + c);
    const __half2* a2 = (const __half2*)(g_eo + (size_t)g_slot[t * 2 + 0] * DM + c);
    const __half2* b2 = (const __half2*)(g_eo + (size_t)g_slot[t * 2 + 1] * DM + c);
    float2 a01 = __half22float2(a2[0]), a23 = __half22float2(a2[1]);
    float2 b01 = __half22float2(b2[0]), b23 = __half22float2(b2[1]);
    float w0 = g_tg[t * 2 + 0], w1 = g_tg[t * 2 + 1];
    float v[4] = {x4.x + w0 * a01.x + w1 * b01.x, x4.y + w0 * a01.y + w1 * b01.y,
                  x4.z + w0 * a23.x + w1 * b23.x, x4.w + w0 * a23.y + w1 * b23.y};
    float s = v[0] + v[1] + v[2] + v[3];
#pragma unroll
    for (int o = 16; o > 0; o >>= 1) s += __shfl_xor_sync(0xffffffffu, s, o);
    if ((tid & 31) == 0) red[tid >> 5] = s;
    __syncthreads();
    float tot = 0.f;
#pragma unroll
    for (int i = 0; i < 8; i++) tot += red[i];
    float mu = tot * (1.f / DM);
    float s2 = 0.f;
#pragma unroll
    for (int i = 0; i < 4; i++) { float d = v[i] - mu; s2 += d * d; }
#pragma unroll
    for (int o = 16; o > 0; o >>= 1) s2 += __shfl_xor_sync(0xffffffffu, s2, o);
    __syncthreads();
    if ((tid & 31) == 0) red[tid >> 5] = s2;
    __syncthreads();
    float tot2 = 0.f;
#pragma unroll
    for (int i = 0; i < 8; i++) tot2 += red[i];
    float inv = rsqrtf(tot2 * (1.f / DM) + LN_EPS);
    const float4 gm = *(const float4*)(gamma + c);
    const float4 bt = *(const float4*)(beta + c);
    float4 o4;
    o4.x = (v[0] - mu) * inv * gm.x + bt.x;
    o4.y = (v[1] - mu) * inv * gm.y + bt.y;
    o4.z = (v[2] - mu) * inv * gm.z + bt.z;
    o4.w = (v[3] - mu) * inv * gm.w + bt.w;
    *(float4*)(out + (size_t)t * DM + c) = o4;
    if (t == 0 && tid == 0 && out_size > T_TOK * DM) {
        const float tt = 1.f / NE;
        float loss = 0.f;
        for (int e = 0; e < NE; e++)
            loss += tt * (logf(tt) - logf(g_psum[e] / (float)T_TOK + 1e-8f));
        out[T_TOK * DM] = loss;
    }
}

// ---------------- launch ----------------
extern "C" void kernel_launch(void* const* d_in, const int* in_sizes, int n_in,
                              void* d_out, int out_size) {
    const float* x      = (const float*)d_in[0];
    const float* gw1    = (const float*)d_in[1];
    const float* gb1    = (const float*)d_in[2];
    const float* gw2    = (const float*)d_in[3];
    const float* gb2    = (const float*)d_in[4];
    const float* we1    = (const float*)d_in[5];
    const float* be1    = (const float*)d_in[6];
    const float* we2    = (const float*)d_in[7];
    const float* be2    = (const float*)d_in[8];
    const float* escale = (const float*)d_in[9];
    const float* ebias  = (const float*)d_in[10];
    const float* gamma  = (const float*)d_in[11];
    const float* beta   = (const float*)d_in[12];
    float* out = (float*)d_out;

    cudaFuncSetAttribute(k_gate1tc, cudaFuncAttributeMaxDynamicSharedMemorySize, EXP_SMEM);
    cudaFuncSetAttribute(k_exp_fused, cudaFuncAttributeMaxDynamicSharedMemorySize, EXP_SMEM);

    // fork: expert-weight transposes on side stream (consumed only by the fused expert kernel)
    cudaEventRecord(g_evA, 0);
    cudaStreamWaitEvent(g_s2, g_evA, 0);
    {
        __half* w1h; cudaGetSymbolAddress((void**)&w1h, g_w1h);
        __half* w2h; cudaGetSymbolAddress((void**)&w2h, g_w2h);
        k_trcvt<<<dim3(DF / 32, DM / 32, NE), dim3(32, 8), 0, g_s2>>>(we1, w1h, DM, DF);
        k_trcvt<<<dim3(DM / 32, DF / 32, NE), dim3(32, 8), 0, g_s2>>>(we2, w2h, DF, DM);
    }
    cudaEventRecord(g_evB, g_s2);

    // main stream: prep + gating chain (overlapped with the transposes)
    k_prep<<<PREP_CVT_BLOCKS + 512, 256>>>(x, gw1);
    k_gate1tc<<<dim3(GHID / 128, T_TOK / 128), 256, EXP_SMEM>>>(gb1);
    k_gate2<<<T_TOK / 8, 256>>>(gw2, gb2);

    // join, then fused grouped expert FFN (exp1 + exp2 in one grid, spin-wait dep)
    cudaStreamWaitEvent(0, g_evB, 0);
    k_exp_fused<<<EXP1_BLOCKS + EXP2_BLOCKS, 256, EXP_SMEM>>>(be1, be2, escale, ebias);

    // combine + residual + LayerNorm + loss
    k_ln<<<T_TOK, 256>>>(x, gamma, beta, out, out_size);
}

// round 15
// speedup vs baseline: 1.0269x; 1.0269x over previous
#include <cuda_runtime.h>
#include <cuda_fp16.h>
#include <cstdint>
#include <math.h>

// ---------------- problem constants ----------------
#define T_TOK 8192      // B*S
#define DM    1024
#define DF    4096
#define NE    8
#define GHID  512
#define LN_EPS 1e-5f
#define KG1   (3*DM)    // split-gate1 K' = 3072
#define CAP   8192      // fixed slots per expert

// ---------------- device scratch ----------------
__device__ float  g_gh[T_TOK * GHID];                 // gating hidden (fp32)
__device__ __half g_xh[(size_t)T_TOK * DM];           // fp16 x (hi)
__device__ __half g_xlo[(size_t)T_TOK * DM];          // fp16 x residual (lo)
__device__ __half g_gw1h[(size_t)GHID * KG1];         // [n=512][k'=3072] = [whi|wlo|whi]
__device__ __half g_w1h[(size_t)NE * DF * DM];        // [E][n=F][k=D]
__device__ __half g_w2h[(size_t)NE * DM * DF];        // [E][n=D][k=F]
__device__ __half g_hbuf[(size_t)NE * CAP * DF];      // fp16 hidden (fixed-capacity groups)
__device__ __half g_eo1[(size_t)NE * CAP * DM];       // exp2 partial, K-half 0 (fp16)
__device__ __half g_eo2[(size_t)NE * CAP * DM];       // exp2 partial, K-half 1 (fp16)
__device__ int    g_cur[NE];
__device__ int    g_rdy[NE * 64];                     // exp1 row-tile completion counters
__device__ float  g_tg[T_TOK * 2];
__device__ int    g_slot[T_TOK * 2];
__device__ int    g_tok[NE * CAP];
__device__ float  g_psum[NE];

// ---------------- side stream for overlap (host-side resources only) ----------------
static cudaStream_t g_s2;
static cudaEvent_t g_evA, g_evB;
namespace {
struct StreamInit {
    StreamInit() {
        cudaStreamCreateWithFlags(&g_s2, cudaStreamNonBlocking);
        cudaEventCreateWithFlags(&g_evA, cudaEventDisableTiming);
        cudaEventCreateWithFlags(&g_evB, cudaEventDisableTiming);
    }
};
StreamInit g_si;
}

// ---------------- PTX helpers ----------------
__device__ __forceinline__ void mma_f16(float* c, const uint32_t* a, const uint32_t* b) {
    asm volatile(
        "mma.sync.aligned.m16n8k16.row.col.f32.f16.f16.f32 "
        "{%0,%1,%2,%3},{%4,%5,%6,%7},{%8,%9},{%0,%1,%2,%3};"
        : "+f"(c[0]), "+f"(c[1]), "+f"(c[2]), "+f"(c[3])
        : "r"(a[0]), "r"(a[1]), "r"(a[2]), "r"(a[3]), "r"(b[0]), "r"(b[1]));
}
__device__ __forceinline__ void ldsm4(uint32_t& a, uint32_t& b, uint32_t& c, uint32_t& d,
                                      uint32_t addr) {
    asm volatile("ldmatrix.sync.aligned.m8n8.x4.shared.b16 {%0,%1,%2,%3}, [%4];"
                 : "=r"(a), "=r"(b), "=r"(c), "=r"(d) : "r"(addr));
}
__device__ __forceinline__ void cp16(void* smem, const void* g) {
    uint32_t s = (uint32_t)__cvta_generic_to_shared(smem);
    asm volatile("cp.async.cg.shared.global [%0],[%1],16;" :: "r"(s), "l"(g));
}
__device__ __forceinline__ void cp_commit() { asm volatile("cp.async.commit_group;"); }
__device__ __forceinline__ void cp_wait1() { asm volatile("cp.async.wait_group 1;"); }
__device__ __forceinline__ void cp_wait0() { asm volatile("cp.async.wait_group 0;"); }
__device__ __forceinline__ uint32_t smem_u32(const void* p) {
    uint32_t a;
    asm("{ .reg .u64 t; cvta.to.shared.u64 t, %1; cvt.u32.u64 %0, t; }" : "=r"(a) : "l"(p));
    return a;
}

// smem geometry: rows of 32 data halves padded to 40 (conflict-free; proven R8)
#define HPITCH 40
#define BKH    32
#define STG_H   (128 * HPITCH)
#define STAGE_H (2 * STG_H)
#define NSTAGE  3
#define EXP_SMEM (NSTAGE * STAGE_H * 2)   // 61440 B dynamic

// ---------------- prep: x hi/lo split + gw1 split-transpose + counter zero ----------------
#define PREP_CVT_BLOCKS (T_TOK * DM / 4 / 256)   // 8192
__global__ void k_prep(const float* __restrict__ x, const float* __restrict__ gw1) {
    int b = blockIdx.x, tid = threadIdx.x;
    if (b < PREP_CVT_BLOCKS) {
        if (b == 0 && tid < NE) { g_cur[tid] = 0; g_psum[tid] = 0.f; }
        if (b == 1) { g_rdy[tid] = 0; g_rdy[tid + 256] = 0; }
        int i = (b * 256 + tid) * 4;
        float4 v = *(const float4*)(x + i);
        __half h[4] = {__float2half_rn(v.x), __float2half_rn(v.y),
                       __float2half_rn(v.z), __float2half_rn(v.w)};
        __half l[4] = {__float2half_rn(v.x - __half2float(h[0])),
                       __float2half_rn(v.y - __half2float(h[1])),
                       __float2half_rn(v.z - __half2float(h[2])),
                       __float2half_rn(v.w - __half2float(h[3]))};
        *(uint2*)(g_xh + i) = *(uint2*)h;
        *(uint2*)(g_xlo + i) = *(uint2*)l;
    } else {
        __shared__ float t[32][33];
        int tb = b - PREP_CVT_BLOCKS;                 // [0, 512)
        int c0 = (tb & 15) * 32, r0 = (tb >> 4) * 32; // c = n, r = k
        int tx = tid & 31, ty = tid >> 5;
#pragma unroll
        for (int i = 0; i < 32; i += 8)
            t[ty + i][tx] = gw1[(size_t)(r0 + ty + i) * GHID + c0 + tx];
        __syncthreads();
#pragma unroll
        for (int i = 0; i < 32; i += 8) {
            int n = c0 + ty + i, k = r0 + tx;
            float v = t[tx][ty + i];
            __half hi = __float2half_rn(v);
            __half lo = __float2half_rn(v - __half2float(hi));
            g_gw1h[(size_t)n * KG1 + k] = hi;
            g_gw1h[(size_t)n * KG1 + DM + k] = lo;
            g_gw1h[(size_t)n * KG1 + 2 * DM + k] = hi;
        }
    }
}

// ---------------- weight transpose+convert: src[e][k][n] -> dst[e][n][k] fp16 ----------------
__global__ void k_trcvt(const float* __restrict__ src, __half* __restrict__ dst,
                        int R /*k*/, int C /*n*/) {
    __shared__ float t[32][33];
    size_t eb = (size_t)blockIdx.z * R * C;
    int c0 = blockIdx.x * 32, r0 = blockIdx.y * 32;
    int tx = threadIdx.x, ty = threadIdx.y;
#pragma unroll
    for (int i = 0; i < 32; i += 8)
        t[ty + i][tx] = src[eb + (size_t)(r0 + ty + i) * C + c0 + tx];
    __syncthreads();
#pragma unroll
    for (int i = 0; i < 32; i += 8)
        dst[eb + (size_t)(c0 + ty + i) * R + r0 + tx] = __float2half_rn(t[tx][ty + i]);
}

// ---------------- gating GEMM2 + top2 + softmax + fused scatter ----------------
__global__ void k_gate2(const float* __restrict__ gw2, const float* __restrict__ gb2) {
    __shared__ float s_ps[NE];
    int tid = threadIdx.x, lane = tid & 31, w = tid >> 5;
    if (tid < NE) s_ps[tid] = 0.f;
    __syncthreads();
    int t = blockIdx.x * 8 + w;
    float acc[NE] = {};
    const float* gr = g_gh + (size_t)t * GHID;
    for (int j = lane; j < GHID; j += 32) {
        float v = gr[j];
#pragma unroll
        for (int e = 0; e < NE; e++) acc[e] += v * gw2[j * NE + e];
    }
#pragma unroll
    for (int e = 0; e < NE; e++)
#pragma unroll
        for (int o = 16; o > 0; o >>= 1) acc[e] += __shfl_xor_sync(0xffffffffu, acc[e], o);
    if (lane == 0) {
        float lg[NE];
        float m = -1e30f;
#pragma unroll
        for (int e = 0; e < NE; e++) { lg[e] = acc[e] + gb2[e]; m = fmaxf(m, lg[e]); }
        int i1 = 0, i2 = -1; float v1 = -1e30f, v2 = -1e30f;
#pragma unroll
        for (int e = 0; e < NE; e++) {
            float v = lg[e];
            if (v > v1) { v2 = v1; i2 = i1; v1 = v; i1 = e; }
            else if (v > v2) { v2 = v; i2 = e; }
        }
        float ex = expf(v2 - v1);
        float inv2 = 1.f / (1.f + ex);
        g_tg[t * 2 + 0] = inv2; g_tg[t * 2 + 1] = ex * inv2;
        int p1 = atomicAdd(&g_cur[i1], 1);
        int p2 = atomicAdd(&g_cur[i2], 1);
        int s1 = i1 * CAP + p1, s2 = i2 * CAP + p2;
        g_tok[s1] = t; g_tok[s2] = t;
        g_slot[t * 2 + 0] = s1; g_slot[t * 2 + 1] = s2;
        float se = 0.f, pe[NE];
#pragma unroll
        for (int e = 0; e < NE; e++) { pe[e] = expf(lg[e] - m); se += pe[e]; }
        float inv = 1.f / se;
#pragma unroll
        for (int e = 0; e < NE; e++) atomicAdd(&s_ps[e], pe[e] * inv);
    }
    __syncthreads();
    if (tid < NE) atomicAdd(&g_psum[tid], s_ps[tid]);
}

// =======================================================================
// fp16 mma.sync GEMM body (R8-proven geometry).
// MODE 0: hbuf(fp16) = gelu(gather(xh) @ w1h^T + be1)      (K = DM)
// MODE 1: eo-half(fp16) = split-K exp2 partial             (K = DF/2, koff 0/2048)
//         koff==0:  eo1 = acc*escale
//         koff!=0:  eo2 = (acc + be2)*escale + ebias
// MODE 2: gh(fp32) = relu([xhi|xhi|xlo] @ gw1h^T + gb1)    (K = 3072)
// =======================================================================
template <int MODE>
__device__ __forceinline__ void gemm_body(__half* sm, int e, int row0, int col0, int cnt,
                                          int koff, __half* __restrict__ eobuf,
                                          const float* __restrict__ p1,
                                          const float* __restrict__ p2,
                                          const float* __restrict__ p3) {
    int off = (MODE == 2) ? 0 : e * CAP;
    int tid = threadIdx.x, lane = tid & 31, wid = tid >> 5;
    int m0w = (wid >> 2) * 64;
    int n0w = (wid & 3) * 32;

    const int KD = (MODE == 0) ? DM : (MODE == 1 ? DF / 2 : KG1);
    int r = tid >> 1, cp0h = (tid & 1) * 16;
    int arow = row0 + r;
    int arc = arow < cnt ? arow : cnt - 1;
    const __half* arp_hi;
    const __half* arp_lo = nullptr;
    if (MODE == 0)      arp_hi = g_xh + (size_t)g_tok[off + arc] * DM;
    else if (MODE == 1) arp_hi = g_hbuf + (size_t)(off + arc) * DF + koff;
    else { arp_hi = g_xh + (size_t)arc * DM; arp_lo = g_xlo + (size_t)arc * DM; }
    const __half* brp = (MODE == 2)
        ? (g_gw1h + (size_t)(col0 + r) * KG1)
        : ((MODE ? g_w2h : g_w1h) + (size_t)e * DM * DF +
           (size_t)(col0 + r) * (MODE ? DF : DM) + (MODE ? koff : 0));
    int ldo = r * HPITCH + cp0h;

    int lr = lane & 7;
    int a_radd = ((lane >> 3) & 1) * 8 + lr, a_kadd = (lane >> 4) * 8;
    int b_radd = (lane >> 4) * 8 + lr, b_kadd = ((lane >> 3) & 1) * 8;
    int a_off[4], b_off[2];
#pragma unroll
    for (int mi = 0; mi < 4; mi++) a_off[mi] = (m0w + mi * 16 + a_radd) * HPITCH + a_kadd;
#pragma unroll
    for (int ni = 0; ni < 2; ni++) b_off[ni] = (n0w + ni * 16 + b_radd) * HPITCH + b_kadd;
    uint32_t smu = smem_u32(sm);

    float acc[4][4][4] = {};

    const int NIT = KD / BKH;
#pragma unroll
    for (int s = 0; s < 2; s++) {
        int k0 = s * BKH;
        const __half* as;
        if (MODE == 2) as = (k0 < 2 * DM ? arp_hi + (k0 & (DM - 1)) : arp_lo + (k0 - 2 * DM)) + cp0h;
        else           as = arp_hi + k0 + cp0h;
        __half* ad = sm + s * STAGE_H + ldo;
        __half* bd = sm + s * STAGE_H + STG_H + ldo;
        cp16(ad, as); cp16(ad + 8, as + 8);
        cp16(bd, brp + k0 + cp0h); cp16(bd + 8, brp + k0 + cp0h + 8);
        cp_commit();
    }

    int st = 0;
    for (int it = 0; it < NIT; it++) {
        if (it < NIT - 2) cp_wait1(); else cp_wait0();
        __syncthreads();
        if (it + 2 < NIT) {
            int k0 = (it + 2) * BKH;
            int ws = st + 2 >= NSTAGE ? st + 2 - NSTAGE : st + 2;
            const __half* as;
            if (MODE == 2) as = (k0 < 2 * DM ? arp_hi + (k0 & (DM - 1)) : arp_lo + (k0 - 2 * DM)) + cp0h;
            else           as = arp_hi + k0 + cp0h;
            __half* ad = sm + ws * STAGE_H + ldo;
            __half* bd = sm + ws * STAGE_H + STG_H + ldo;
            cp16(ad, as); cp16(ad + 8, as + 8);
            cp16(bd, brp + k0 + cp0h); cp16(bd + 8, brp + k0 + cp0h + 8);
            cp_commit();
        }
        uint32_t stA = smu + (uint32_t)(st * STAGE_H) * 2;
        uint32_t stB = stA + (uint32_t)STG_H * 2;
#pragma unroll
        for (int q = 0; q < BKH; q += 16) {
            uint32_t af[4][4], bf[4][2];
#pragma unroll
            for (int mi = 0; mi < 4; mi++)
                ldsm4(af[mi][0], af[mi][1], af[mi][2], af[mi][3],
                      stA + (uint32_t)(a_off[mi] + q) * 2);
#pragma unroll
            for (int np = 0; np < 2; np++)
                ldsm4(bf[2 * np][0], bf[2 * np][1], bf[2 * np + 1][0], bf[2 * np + 1][1],
                      stB + (uint32_t)(b_off[np] + q) * 2);
#pragma unroll
            for (int mi = 0; mi < 4; mi++)
#pragma unroll
                for (int ni = 0; ni < 4; ni++) mma_f16(acc[mi][ni], af[mi], bf[ni]);
        }
        st = st + 1 == NSTAGE ? 0 : st + 1;
    }

    int gr = lane >> 2, c2 = (lane & 3) * 2;
#pragma unroll
    for (int mi = 0; mi < 4; mi++) {
#pragma unroll
        for (int half = 0; half < 2; half++) {
            int rr = row0 + m0w + mi * 16 + gr + half * 8;
            if (rr < cnt) {
                if (MODE == 0) {
                    __half* orow = g_hbuf + (size_t)(off + rr) * DF;
                    const float* bb = p1 + e * DF;
#pragma unroll
                    for (int ni = 0; ni < 4; ni++) {
                        int c = col0 + n0w + ni * 8 + c2;
                        float v0 = acc[mi][ni][half * 2 + 0] + bb[c];
                        float v1 = acc[mi][ni][half * 2 + 1] + bb[c + 1];
                        v0 = 0.5f * v0 * (1.f + erff(v0 * 0.70710678118654752f));
                        v1 = 0.5f * v1 * (1.f + erff(v1 * 0.70710678118654752f));
                        *(__half2*)(orow + c) = __floats2half2_rn(v0, v1);
                    }
                } else if (MODE == 1) {
                    __half* orow = eobuf + (size_t)(off + rr) * DM;
                    const float* bb = p1 + e * DM;
                    const float* ss = p2 + e * DM;
                    const float* eb = p3 + e * DM;
#pragma unroll
                    for (int ni = 0; ni < 4; ni++) {
                        int c = col0 + n0w + ni * 8 + c2;
                        float v0, v1;
                        if (koff == 0) {
                            v0 = acc[mi][ni][half * 2 + 0] * ss[c];
                            v1 = acc[mi][ni][half * 2 + 1] * ss[c + 1];
                        } else {
                            v0 = (acc[mi][ni][half * 2 + 0] + bb[c]) * ss[c] + eb[c];
                            v1 = (acc[mi][ni][half * 2 + 1] + bb[c + 1]) * ss[c + 1] + eb[c + 1];
                        }
                        *(__half2*)(orow + c) = __floats2half2_rn(v0, v1);
                    }
                } else {
                    float* orow = g_gh + (size_t)rr * GHID;
                    const float* bb = p1;   // gb1
#pragma unroll
                    for (int ni = 0; ni < 4; ni++) {
                        int c = col0 + n0w + ni * 8 + c2;
                        float v0 = fmaxf(acc[mi][ni][half * 2 + 0] + bb[c], 0.f);
                        float v1 = fmaxf(acc[mi][ni][half * 2 + 1] + bb[c + 1], 0.f);
                        *(float2*)(orow + c) = make_float2(v0, v1);
                    }
                }
            }
        }
    }
}

// ---------------- gating GEMM1 wrapper (MODE 2, dense) ----------------
__global__ __launch_bounds__(256, 2) void k_gate1tc(const float* __restrict__ gb1) {
    extern __shared__ __half sm[];
    gemm_body<2>(sm, 0, blockIdx.y * 128, blockIdx.x * 128, T_TOK, 0, nullptr,
                 gb1, nullptr, nullptr);
}

// ---------------- fused expert FFN: exp1 + split-K exp2, spin-wait dependency ----------------
#define EXP1_BLOCKS (32 * 64 * NE)    // 16384
#define EXP2_BLOCKS (8 * 64 * 2 * NE) // 8192 (2 K-halves)
__global__ __launch_bounds__(256, 2) void k_exp_fused(const float* __restrict__ be1,
                                                      const float* __restrict__ be2,
                                                      const float* __restrict__ escale,
                                                      const float* __restrict__ ebias) {
    extern __shared__ __half sm[];
    int bid = blockIdx.x;
    if (bid < EXP1_BLOCKS) {
        int col = (bid & 31) * 128, row = (bid >> 5) & 63, e = bid >> 11;
        int cnt = g_cur[e];
        if (row * 128 >= cnt) return;
        gemm_body<0>(sm, e, row * 128, col, cnt, 0, nullptr, be1, nullptr, nullptr);
        __syncthreads();
        if (threadIdx.x == 0) {
            __threadfence();
            atomicAdd(&g_rdy[e * 64 + row], 1);
        }
    } else {
        int b2 = bid - EXP1_BLOCKS;
        int col = (b2 & 7) * 128, row = (b2 >> 3) & 63;
        int half = (b2 >> 9) & 1, e = b2 >> 10;
        int cnt = g_cur[e];
        if (row * 128 >= cnt) return;
        if (threadIdx.x == 0) {
            while (*(volatile int*)&g_rdy[e * 64 + row] < 32) __nanosleep(64);
            __threadfence();
        }
        __syncthreads();
        gemm_body<1>(sm, e, row * 128, col, cnt, half * (DF / 2),
                     half ? g_eo2 : g_eo1, be2, escale, ebias);
    }
}

// ---------------- final: combine top-2 (2 K-halves each) + residual + LN + loss ----------------
__global__ void k_ln(const float* __restrict__ x, const float* __restrict__ gamma,
                     const float* __restrict__ beta, float* __restrict__ out, int out_size) {
    int t = blockIdx.x;
    int tid = threadIdx.x;
    __shared__ float red[8];
    int c = tid * 4;
    size_t s0 = (size_t)g_slot[t * 2 + 0] * DM + c;
    size_t s1 = (size_t)g_slot[t * 2 + 1] * DM + c;
    const float4 x4 = *(const float4*)(x + (size_t)t * DM + c);
    const __half2* a1 = (const __half2*)(g_eo1 + s0);
    const __half2* a2 = (const __half2*)(g_eo2 + s0);
    const __half2* b1 = (const __half2*)(g_eo1 + s1);
    const __half2* b2 = (const __half2*)(g_eo2 + s1);
    float2 aA = __half22float2(a1[0]), aB = __half22float2(a1[1]);
    float2 aC = __half22float2(a2[0]), aD = __half22float2(a2[1]);
    float2 bA = __half22float2(b1[0]), bB = __half22float2(b1[1]);
    float2 bC = __half22float2(b2[0]), bD = __half22float2(b2[1]);
    float w0 = g_tg[t * 2 + 0], w1 = g_tg[t * 2 + 1];
    float v[4] = {x4.x + w0 * (aA.x + aC.x) + w1 * (bA.x + bC.x),
                  x4.y + w0 * (aA.y + aC.y) + w1 * (bA.y + bC.y),
                  x4.z + w0 * (aB.x + aD.x) + w1 * (bB.x + bD.x),
                  x4.w + w0 * (aB.y + aD.y) + w1 * (bB.y + bD.y)};
    float s = v[0] + v[1] + v[2] + v[3];
#pragma unroll
    for (int o = 16; o > 0; o >>= 1) s += __shfl_xor_sync(0xffffffffu, s, o);
    if ((tid & 31) == 0) red[tid >> 5] = s;
    __syncthreads();
    float tot = 0.f;
#pragma unroll
    for (int i = 0; i < 8; i++) tot += red[i];
    float mu = tot * (1.f / DM);
    float s2 = 0.f;
#pragma unroll
    for (int i = 0; i < 4; i++) { float d = v[i] - mu; s2 += d * d; }
#pragma unroll
    for (int o = 16; o > 0; o >>= 1) s2 += __shfl_xor_sync(0xffffffffu, s2, o);
    __syncthreads();
    if ((tid & 31) == 0) red[tid >> 5] = s2;
    __syncthreads();
    float tot2 = 0.f;
#pragma unroll
    for (int i = 0; i < 8; i++) tot2 += red[i];
    float inv = rsqrtf(tot2 * (1.f / DM) + LN_EPS);
    const float4 gm = *(const float4*)(gamma + c);
    const float4 bt = *(const float4*)(beta + c);
    float4 o4;
    o4.x = (v[0] - mu) * inv * gm.x + bt.x;
    o4.y = (v[1] - mu) * inv * gm.y + bt.y;
    o4.z = (v[2] - mu) * inv * gm.z + bt.z;
    o4.w = (v[3] - mu) * inv * gm.w + bt.w;
    *(float4*)(out + (size_t)t * DM + c) = o4;
    if (t == 0 && tid == 0 && out_size > T_TOK * DM) {
        const float tt = 1.f / NE;
        float loss = 0.f;
        for (int e = 0; e < NE; e++)
            loss += tt * (logf(tt) - logf(g_psum[e] / (float)T_TOK + 1e-8f));
        out[T_TOK * DM] = loss;
    }
}

// ---------------- launch ----------------
extern "C" void kernel_launch(void* const* d_in, const int* in_sizes, int n_in,
                              void* d_out, int out_size) {
    const float* x      = (const float*)d_in[0];
    const float* gw1    = (const float*)d_in[1];
    const float* gb1    = (const float*)d_in[2];
    const float* gw2    = (const float*)d_in[3];
    const float* gb2    = (const float*)d_in[4];
    const float* we1    = (const float*)d_in[5];
    const float* be1    = (const float*)d_in[6];
    const float* we2    = (const float*)d_in[7];
    const float* be2    = (const float*)d_in[8];
    const float* escale = (const float*)d_in[9];
    const float* ebias  = (const float*)d_in[10];
    const float* gamma  = (const float*)d_in[11];
    const float* beta   = (const float*)d_in[12];
    float* out = (float*)d_out;

    cudaFuncSetAttribute(k_gate1tc, cudaFuncAttributeMaxDynamicSharedMemorySize, EXP_SMEM);
    cudaFuncSetAttribute(k_exp_fused, cudaFuncAttributeMaxDynamicSharedMemorySize, EXP_SMEM);

    // fork: expert-weight transposes on side stream (consumed only by the fused expert kernel)
    cudaEventRecord(g_evA, 0);
    cudaStreamWaitEvent(g_s2, g_evA, 0);
    {
        __half* w1h; cudaGetSymbolAddress((void**)&w1h, g_w1h);
        __half* w2h; cudaGetSymbolAddress((void**)&w2h, g_w2h);
        k_trcvt<<<dim3(DF / 32, DM / 32, NE), dim3(32, 8), 0, g_s2>>>(we1, w1h, DM, DF);
        k_trcvt<<<dim3(DM / 32, DF / 32, NE), dim3(32, 8), 0, g_s2>>>(we2, w2h, DF, DM);
    }
    cudaEventRecord(g_evB, g_s2);

    // main stream: prep + gating chain (overlapped with the transposes)
    k_prep<<<PREP_CVT_BLOCKS + 512, 256>>>(x, gw1);
    k_gate1tc<<<dim3(GHID / 128, T_TOK / 128), 256, EXP_SMEM>>>(gb1);
    k_gate2<<<T_TOK / 8, 256>>>(gw2, gb2);

    // join, then fused grouped expert FFN (exp1 + split-K exp2, spin-wait dep)
    cudaStreamWaitEvent(0, g_evB, 0);
    k_exp_fused<<<EXP1_BLOCKS + EXP2_BLOCKS, 256, EXP_SMEM>>>(be1, be2, escale, ebias);

    // combine + residual + LayerNorm + loss
    k_ln<<<T_TOK, 256>>>(x, gamma, beta, out, out_size);
}